// round 4
// baseline (speedup 1.0000x reference)
#include <cuda_runtime.h>
#include <cstdint>

#define B_DIM 2048
#define N_DIM 512
#define C_DIM 64
#define L_DIM 2
#define O_DIM 8192
#define LO (L_DIM * O_DIM)      // 16384
#define LO4 (LO / 4)            // 4096

#define BPB 4                   // batches per gather block
#define CHUNK 2048              // lo per gather block
#define CHUNK4 (CHUNK / 4)      // 512 int4 per chunk
#define NCHUNK (LO / CHUNK)     // 8

// Selection table sel[l*O + o] = input-feature index (0..N-1)
__device__ int g_sel[LO];

// ---------------------------------------------------------------------------
// Kernel 1: argmax over C=64 candidates per (l,o), 4-way candidate split +
// shfl reduce. Each thread handles 4 lo (float4) and 16 candidates.
// First-max-wins tiebreak matches jnp.argmax (smaller candidate index).
// ---------------------------------------------------------------------------
__global__ void __launch_bounds__(256) build_sel_kernel(
    const float4* __restrict__ w4, const int* __restrict__ idx) {
    int g = blockIdx.x * blockDim.x + threadIdx.x;   // [0, 16384)
    int lo4 = g >> 2;                                // [0, 4096)
    int q   = g & 3;                                 // candidate quarter

    float best[4];
    int   bc[4];
    int c0 = q * 16;
    {
        float4 v = __ldg(w4 + (size_t)c0 * LO4 + lo4);
        best[0] = v.x; best[1] = v.y; best[2] = v.z; best[3] = v.w;
        bc[0] = bc[1] = bc[2] = bc[3] = c0;
    }
#pragma unroll
    for (int j = 1; j < 16; ++j) {
        int c = c0 + j;
        float4 v = __ldg(w4 + (size_t)c * LO4 + lo4);
        if (v.x > best[0]) { best[0] = v.x; bc[0] = c; }
        if (v.y > best[1]) { best[1] = v.y; bc[1] = c; }
        if (v.z > best[2]) { best[2] = v.z; bc[2] = c; }
        if (v.w > best[3]) { best[3] = v.w; bc[3] = c; }
    }
    // reduce across the 4 q-lanes (low 2 bits of lane id)
#pragma unroll
    for (int d = 1; d < 4; d <<= 1) {
#pragma unroll
        for (int k = 0; k < 4; ++k) {
            float ob = __shfl_xor_sync(0xFFFFFFFFu, best[k], d);
            int   oc = __shfl_xor_sync(0xFFFFFFFFu, bc[k], d);
            if (ob > best[k] || (ob == best[k] && oc < bc[k])) {
                best[k] = ob; bc[k] = oc;
            }
        }
    }
    if (q == 0) {
#pragma unroll
        for (int k = 0; k < 4; ++k) {
            int lo = lo4 * 4 + k;
            g_sel[lo] = __ldg(idx + bc[k] * LO + lo);
        }
    }
}

// ---------------------------------------------------------------------------
// Kernel 2: out[b, lo] = x[b, sel[lo]].
// Stage 4 batch rows interleaved (xq[n] = float4 of x[b0..b3][n]), gather
// with LDS.128 (fetches the same column for 4 batches in one access, lower
// effective bank-conflict cost), transpose 4x4 in registers, store 4
// coalesced STG.128.
// ---------------------------------------------------------------------------
__global__ void __launch_bounds__(256) gather_kernel(
    const float* __restrict__ x, float4* __restrict__ out4) {
    __shared__ float4 xq[N_DIM];

    int b0    = (blockIdx.x >> 3) * BPB;      // / NCHUNK
    int chunk = blockIdx.x & (NCHUNK - 1);

    const float* xr0 = x + (size_t)b0 * N_DIM;
    // stage interleaved rows: thread t fills columns t and t+256
#pragma unroll
    for (int r = 0; r < 2; ++r) {
        int n = r * 256 + threadIdx.x;
        float4 v;
        v.x = __ldg(xr0 + n);
        v.y = __ldg(xr0 + N_DIM + n);
        v.z = __ldg(xr0 + 2 * N_DIM + n);
        v.w = __ldg(xr0 + 3 * N_DIM + n);
        xq[n] = v;
    }
    __syncthreads();

    const int4* sel4 = (const int4*)g_sel + chunk * CHUNK4;

#pragma unroll
    for (int r = 0; r < 2; ++r) {
        int i = r * 256 + threadIdx.x;        // [0, 512) int4 within chunk
        int4 s = __ldg(sel4 + i);
        float4 a = xq[s.x];
        float4 b = xq[s.y];
        float4 c = xq[s.z];
        float4 d = xq[s.w];
        size_t col = (size_t)chunk * CHUNK4 + i;
        out4[(size_t)(b0 + 0) * LO4 + col] = make_float4(a.x, b.x, c.x, d.x);
        out4[(size_t)(b0 + 1) * LO4 + col] = make_float4(a.y, b.y, c.y, d.y);
        out4[(size_t)(b0 + 2) * LO4 + col] = make_float4(a.z, b.z, c.z, d.z);
        out4[(size_t)(b0 + 3) * LO4 + col] = make_float4(a.w, b.w, c.w, d.w);
    }
}

extern "C" void kernel_launch(void* const* d_in, const int* in_sizes, int n_in,
                              void* d_out, int out_size) {
    const float* x   = (const float*)d_in[0];
    const float* w   = (const float*)d_in[1];
    const int*   idx = (const int*)d_in[2];
    float4* out = (float4*)d_out;

    build_sel_kernel<<<64, 256>>>((const float4*)w, idx);
    gather_kernel<<<(B_DIM / BPB) * NCHUNK, 256>>>(x, out);
}

// round 5
// speedup vs baseline: 1.0110x; 1.0110x over previous
#include <cuda_runtime.h>
#include <cstdint>

#define B_DIM 2048
#define N_DIM 512
#define C_DIM 64
#define L_DIM 2
#define O_DIM 8192
#define LO (L_DIM * O_DIM)      // 16384
#define LO4 (LO / 4)            // 4096

#define BPB 2                   // batches per gather block (float2 interleave)
#define CHUNK 4096              // lo per block
#define CHUNK4 (CHUNK / 4)      // 1024 int4 / float4
#define NCHUNK (LO / CHUNK)     // 4
#define ITERS (CHUNK4 / 256)    // 4 int4 per thread

// Selection table sel[l*O + o] = input-feature index (0..N-1)
__device__ int g_sel[LO];

__device__ __forceinline__ uint32_t smem_u32(const void* p) {
    uint32_t a;
    asm("{ .reg .u64 t; cvta.to.shared.u64 t, %1; cvt.u32.u64 %0, t; }"
        : "=r"(a) : "l"(p));
    return a;
}

// ---------------------------------------------------------------------------
// Kernel 1: argmax over C=64 candidates per (l,o), 4-way candidate split +
// shfl reduce (first-max-wins tiebreak matches jnp.argmax).
// ---------------------------------------------------------------------------
__global__ void __launch_bounds__(256) build_sel_kernel(
    const float4* __restrict__ w4, const int* __restrict__ idx) {
    int g = blockIdx.x * blockDim.x + threadIdx.x;   // [0, 16384)
    int lo4 = g >> 2;
    int q   = g & 3;

    float best[4];
    int   bc[4];
    int c0 = q * 16;
    {
        float4 v = __ldg(w4 + (size_t)c0 * LO4 + lo4);
        best[0] = v.x; best[1] = v.y; best[2] = v.z; best[3] = v.w;
        bc[0] = bc[1] = bc[2] = bc[3] = c0;
    }
#pragma unroll
    for (int j = 1; j < 16; ++j) {
        int c = c0 + j;
        float4 v = __ldg(w4 + (size_t)c * LO4 + lo4);
        if (v.x > best[0]) { best[0] = v.x; bc[0] = c; }
        if (v.y > best[1]) { best[1] = v.y; bc[1] = c; }
        if (v.z > best[2]) { best[2] = v.z; bc[2] = c; }
        if (v.w > best[3]) { best[3] = v.w; bc[3] = c; }
    }
#pragma unroll
    for (int d = 1; d < 4; d <<= 1) {
#pragma unroll
        for (int k = 0; k < 4; ++k) {
            float ob = __shfl_xor_sync(0xFFFFFFFFu, best[k], d);
            int   oc = __shfl_xor_sync(0xFFFFFFFFu, bc[k], d);
            if (ob > best[k] || (ob == best[k] && oc < bc[k])) {
                best[k] = ob; bc[k] = oc;
            }
        }
    }
    if (q == 0) {
#pragma unroll
        for (int k = 0; k < 4; ++k) {
            int lo = lo4 * 4 + k;
            g_sel[lo] = __ldg(idx + bc[k] * LO + lo);
        }
    }
}

// ---------------------------------------------------------------------------
// Kernel 2: out[b, lo] = x[b, sel[lo]] for 2 batches per block.
// - stage x rows interleaved as float2 (one LDS.64 serves both batches)
// - gather into per-batch smem tiles (conflict-free STS.128)
// - bulk-store tiles shared->global via cp.async.bulk (bypasses the
//   per-thread STG wavefront path through L1tex)
// ---------------------------------------------------------------------------
__global__ void __launch_bounds__(256) gather_kernel(
    const float* __restrict__ x, float* __restrict__ out) {
    __shared__ float2 xs2[N_DIM];                // 4 KB
    __shared__ float4 tile[BPB][CHUNK4];         // 2 x 16 KB

    int b0    = (blockIdx.x >> 2) * BPB;         // / NCHUNK
    int chunk = blockIdx.x & (NCHUNK - 1);

    // hoist sel loads (independent of staging) for MLP
    const int4* sel4 = (const int4*)g_sel + chunk * CHUNK4;
    int4 s[ITERS];
#pragma unroll
    for (int it = 0; it < ITERS; ++it)
        s[it] = __ldg(sel4 + it * 256 + threadIdx.x);

    // stage two x rows interleaved
    const float* xr0 = x + (size_t)b0 * N_DIM;
#pragma unroll
    for (int r = 0; r < N_DIM / 256; ++r) {
        int n = r * 256 + threadIdx.x;
        xs2[n] = make_float2(__ldg(xr0 + n), __ldg(xr0 + N_DIM + n));
    }
    __syncthreads();

#pragma unroll
    for (int it = 0; it < ITERS; ++it) {
        int i = it * 256 + threadIdx.x;
        float2 a = xs2[s[it].x];
        float2 b = xs2[s[it].y];
        float2 c = xs2[s[it].z];
        float2 d = xs2[s[it].w];
        tile[0][i] = make_float4(a.x, b.x, c.x, d.x);
        tile[1][i] = make_float4(a.y, b.y, c.y, d.y);
    }
    __syncthreads();
    asm volatile("fence.proxy.async.shared::cta;" ::: "memory");

    if (threadIdx.x == 0) {
#pragma unroll
        for (int r = 0; r < BPB; ++r) {
            float* gdst = out + (size_t)(b0 + r) * LO + chunk * CHUNK;
            uint32_t ssrc = smem_u32(&tile[r][0]);
            asm volatile(
                "cp.async.bulk.global.shared::cta.bulk_group [%0], [%1], %2;"
                :: "l"(gdst), "r"(ssrc), "n"(CHUNK * 4) : "memory");
        }
        asm volatile("cp.async.bulk.commit_group;" ::: "memory");
        asm volatile("cp.async.bulk.wait_group 0;" ::: "memory");
    }
}

extern "C" void kernel_launch(void* const* d_in, const int* in_sizes, int n_in,
                              void* d_out, int out_size) {
    const float* x   = (const float*)d_in[0];
    const float* w   = (const float*)d_in[1];
    const int*   idx = (const int*)d_in[2];
    float* out = (float*)d_out;

    build_sel_kernel<<<64, 256>>>((const float4*)w, idx);
    gather_kernel<<<(B_DIM / BPB) * NCHUNK, 256>>>(x, out);
}

// round 6
// speedup vs baseline: 1.2108x; 1.1976x over previous
#include <cuda_runtime.h>
#include <cstdint>

#define B_DIM 2048
#define N_DIM 512
#define C_DIM 64
#define L_DIM 2
#define O_DIM 8192
#define LO (L_DIM * O_DIM)      // 16384
#define LO4 (LO / 4)            // 4096

#define BPB 4                   // batches per gather block
#define CHUNK 2048              // lo per gather block
#define CHUNK4 (CHUNK / 4)      // 512 int4 per chunk
#define NCHUNK (LO / CHUNK)     // 8

// Selection table sel[l*O + o] = input-feature index (0..N-1)
__device__ int g_sel[LO];

// ---------------------------------------------------------------------------
// Kernel 1: argmax over C=64 candidates per (l,o), 4-way candidate split +
// shfl reduce (first-max-wins tiebreak matches jnp.argmax). 64-thread blocks
// spread the 16384 threads across all SMs (latency-bound phase).
// ---------------------------------------------------------------------------
__global__ void __launch_bounds__(64) build_sel_kernel(
    const float4* __restrict__ w4, const int* __restrict__ idx) {
    int g = blockIdx.x * 64 + threadIdx.x;           // [0, 16384)
    int lo4 = g >> 2;
    int q   = g & 3;

    float best[4];
    int   bc[4];
    int c0 = q * 16;
    {
        float4 v = __ldg(w4 + (size_t)c0 * LO4 + lo4);
        best[0] = v.x; best[1] = v.y; best[2] = v.z; best[3] = v.w;
        bc[0] = bc[1] = bc[2] = bc[3] = c0;
    }
#pragma unroll
    for (int j = 1; j < 16; ++j) {
        int c = c0 + j;
        float4 v = __ldg(w4 + (size_t)c * LO4 + lo4);
        if (v.x > best[0]) { best[0] = v.x; bc[0] = c; }
        if (v.y > best[1]) { best[1] = v.y; bc[1] = c; }
        if (v.z > best[2]) { best[2] = v.z; bc[2] = c; }
        if (v.w > best[3]) { best[3] = v.w; bc[3] = c; }
    }
#pragma unroll
    for (int d = 1; d < 4; d <<= 1) {
#pragma unroll
        for (int k = 0; k < 4; ++k) {
            float ob = __shfl_xor_sync(0xFFFFFFFFu, best[k], d);
            int   oc = __shfl_xor_sync(0xFFFFFFFFu, bc[k], d);
            if (ob > best[k] || (ob == best[k] && oc < bc[k])) {
                best[k] = ob; bc[k] = oc;
            }
        }
    }
    if (q == 0) {
#pragma unroll
        for (int k = 0; k < 4; ++k) {
            int lo = lo4 * 4 + k;
            g_sel[lo] = __ldg(idx + bc[k] * LO + lo);
        }
    }
}

// ---------------------------------------------------------------------------
// Kernel 2: out[b, lo] = x[b, sel[lo]] for 4 batches per block.
// 4-batch-interleaved smem staging (LDS.128 gathers one column for 4 batches),
// 4x4 register transpose, streaming (__stcs) coalesced float4 stores.
// smem = 8KB -> high occupancy.
// ---------------------------------------------------------------------------
__global__ void __launch_bounds__(256) gather_kernel(
    const float* __restrict__ x, float4* __restrict__ out4) {
    __shared__ float4 xq[N_DIM];                 // 8 KB

    int b0    = (blockIdx.x >> 3) * BPB;         // / NCHUNK
    int chunk = blockIdx.x & (NCHUNK - 1);

    // hoist sel loads for MLP (independent of staging)
    const int4* sel4 = (const int4*)g_sel + chunk * CHUNK4;
    int4 s0 = __ldg(sel4 + threadIdx.x);
    int4 s1 = __ldg(sel4 + 256 + threadIdx.x);

    const float* xr0 = x + (size_t)b0 * N_DIM;
#pragma unroll
    for (int r = 0; r < 2; ++r) {
        int n = r * 256 + threadIdx.x;
        float4 v;
        v.x = __ldg(xr0 + n);
        v.y = __ldg(xr0 + N_DIM + n);
        v.z = __ldg(xr0 + 2 * N_DIM + n);
        v.w = __ldg(xr0 + 3 * N_DIM + n);
        xq[n] = v;
    }
    __syncthreads();

#pragma unroll
    for (int r = 0; r < 2; ++r) {
        int i = r * 256 + threadIdx.x;
        int4 s = (r == 0) ? s0 : s1;
        float4 a = xq[s.x];
        float4 b = xq[s.y];
        float4 c = xq[s.z];
        float4 d = xq[s.w];
        size_t col = (size_t)chunk * CHUNK4 + i;
        __stcs(out4 + (size_t)(b0 + 0) * LO4 + col, make_float4(a.x, b.x, c.x, d.x));
        __stcs(out4 + (size_t)(b0 + 1) * LO4 + col, make_float4(a.y, b.y, c.y, d.y));
        __stcs(out4 + (size_t)(b0 + 2) * LO4 + col, make_float4(a.z, b.z, c.z, d.z));
        __stcs(out4 + (size_t)(b0 + 3) * LO4 + col, make_float4(a.w, b.w, c.w, d.w));
    }
}

extern "C" void kernel_launch(void* const* d_in, const int* in_sizes, int n_in,
                              void* d_out, int out_size) {
    const float* x   = (const float*)d_in[0];
    const float* w   = (const float*)d_in[1];
    const int*   idx = (const int*)d_in[2];
    float4* out = (float4*)d_out;

    build_sel_kernel<<<256, 64>>>((const float4*)w, idx);
    gather_kernel<<<(B_DIM / BPB) * NCHUNK, 256>>>(x, out);
}

// round 7
// speedup vs baseline: 1.2269x; 1.0133x over previous
#include <cuda_runtime.h>
#include <cstdint>

#define B_DIM 2048
#define N_DIM 512
#define C_DIM 64
#define L_DIM 2
#define O_DIM 8192
#define LO (L_DIM * O_DIM)      // 16384
#define LO4 (LO / 4)            // 4096

#define BPB 4                   // batches per gather block
#define CHUNK 2048              // lo per gather block
#define CHUNK4 (CHUNK / 4)      // 512 int4 per chunk
#define NCHUNK (LO / CHUNK)     // 8

// Selection table sel[l*O + o] = input-feature index (0..N-1)
__device__ int g_sel[LO];

// ---------------------------------------------------------------------------
// Kernel 1: argmax over C=64 candidates per (l,o), 4-way candidate split +
// shfl reduce (first-max-wins tiebreak matches jnp.argmax). 64-thread blocks
// spread across all SMs. Triggers dependent launch right after its stores.
// ---------------------------------------------------------------------------
__global__ void __launch_bounds__(64) build_sel_kernel(
    const float4* __restrict__ w4, const int* __restrict__ idx) {
    int g = blockIdx.x * 64 + threadIdx.x;           // [0, 16384)
    int lo4 = g >> 2;
    int q   = g & 3;

    float best[4];
    int   bc[4];
    int c0 = q * 16;
    {
        float4 v = __ldg(w4 + (size_t)c0 * LO4 + lo4);
        best[0] = v.x; best[1] = v.y; best[2] = v.z; best[3] = v.w;
        bc[0] = bc[1] = bc[2] = bc[3] = c0;
    }
#pragma unroll
    for (int j = 1; j < 16; ++j) {
        int c = c0 + j;
        float4 v = __ldg(w4 + (size_t)c * LO4 + lo4);
        if (v.x > best[0]) { best[0] = v.x; bc[0] = c; }
        if (v.y > best[1]) { best[1] = v.y; bc[1] = c; }
        if (v.z > best[2]) { best[2] = v.z; bc[2] = c; }
        if (v.w > best[3]) { best[3] = v.w; bc[3] = c; }
    }
#pragma unroll
    for (int d = 1; d < 4; d <<= 1) {
#pragma unroll
        for (int k = 0; k < 4; ++k) {
            float ob = __shfl_xor_sync(0xFFFFFFFFu, best[k], d);
            int   oc = __shfl_xor_sync(0xFFFFFFFFu, bc[k], d);
            if (ob > best[k] || (ob == best[k] && oc < bc[k])) {
                best[k] = ob; bc[k] = oc;
            }
        }
    }
    if (q == 0) {
#pragma unroll
        for (int k = 0; k < 4; ++k) {
            int lo = lo4 * 4 + k;
            g_sel[lo] = __ldg(idx + bc[k] * LO + lo);
        }
    }
    cudaTriggerProgrammaticLaunchCompletion();
}

// ---------------------------------------------------------------------------
// Kernel 2: out[b, lo] = x[b, sel[lo]] for 4 batches per block.
// Launched with programmatic dependent launch: stages x rows (independent of
// sel) while kernel1 drains, then grid-dependency-syncs before reading sel.
// 4-batch-interleaved LDS.128 gather, 4x4 register transpose, coalesced
// streaming float4 stores.
// ---------------------------------------------------------------------------
__global__ void __launch_bounds__(256) gather_kernel(
    const float* __restrict__ x, float4* __restrict__ out4) {
    __shared__ float4 xq[N_DIM];                 // 8 KB

    int b0    = (blockIdx.x >> 3) * BPB;         // / NCHUNK
    int chunk = blockIdx.x & (NCHUNK - 1);

    // stage x rows first — does not depend on kernel1
    const float* xr0 = x + (size_t)b0 * N_DIM;
#pragma unroll
    for (int r = 0; r < 2; ++r) {
        int n = r * 256 + threadIdx.x;
        float4 v;
        v.x = __ldg(xr0 + n);
        v.y = __ldg(xr0 + N_DIM + n);
        v.z = __ldg(xr0 + 2 * N_DIM + n);
        v.w = __ldg(xr0 + 3 * N_DIM + n);
        xq[n] = v;
    }

    // wait for kernel1's g_sel writes to be visible
    cudaGridDependencySynchronize();
    __syncthreads();

    const int4* sel4 = (const int4*)g_sel + chunk * CHUNK4;

#pragma unroll
    for (int r = 0; r < 2; ++r) {
        int i = r * 256 + threadIdx.x;
        int4 s = __ldg(sel4 + i);
        float4 a = xq[s.x];
        float4 b = xq[s.y];
        float4 c = xq[s.z];
        float4 d = xq[s.w];
        size_t col = (size_t)chunk * CHUNK4 + i;
        __stcs(out4 + (size_t)(b0 + 0) * LO4 + col, make_float4(a.x, b.x, c.x, d.x));
        __stcs(out4 + (size_t)(b0 + 1) * LO4 + col, make_float4(a.y, b.y, c.y, d.y));
        __stcs(out4 + (size_t)(b0 + 2) * LO4 + col, make_float4(a.z, b.z, c.z, d.z));
        __stcs(out4 + (size_t)(b0 + 3) * LO4 + col, make_float4(a.w, b.w, c.w, d.w));
    }
}

extern "C" void kernel_launch(void* const* d_in, const int* in_sizes, int n_in,
                              void* d_out, int out_size) {
    const float* x   = (const float*)d_in[0];
    const float* w   = (const float*)d_in[1];
    const int*   idx = (const int*)d_in[2];
    float4* out = (float4*)d_out;

    build_sel_kernel<<<256, 64>>>((const float4*)w, idx);

    // Secondary launch with programmatic dependent launch enabled
    cudaLaunchAttribute attrs[1];
    attrs[0].id = cudaLaunchAttributeProgrammaticStreamSerialization;
    attrs[0].val.programmaticStreamSerializationAllowed = 1;

    cudaLaunchConfig_t cfg = {};
    cfg.gridDim  = dim3((B_DIM / BPB) * NCHUNK);
    cfg.blockDim = dim3(256);
    cfg.dynamicSmemBytes = 0;
    cfg.stream = 0;
    cfg.attrs = attrs;
    cfg.numAttrs = 1;

    cudaLaunchKernelEx(&cfg, gather_kernel, x, out);
}